// round 16
// baseline (speedup 1.0000x reference)
#include <cuda_runtime.h>
#include <cuda_bf16.h>
#include <cstdint>
#include <math.h>

#define BB   32
#define NPTS 2048
#define SA   512
#define SBp  256
#define KNB  32

// ---------------- scratch (device globals; no allocations allowed) ----------------
__device__ __align__(16) float g_bufA[67108864];   // 268MB
__device__ __align__(16) float g_bufB[67108864];   // 268MB
__device__ __align__(16) float g_xyz [BB*NPTS*3];
__device__ __align__(16) float g_f   [BB*NPTS*64];
__device__ __align__(16) float g_xyz1[BB*SA*3];
__device__ __align__(16) float g_xyz2[BB*SBp*3];
__device__ __align__(16) float g_f1  [BB*SA*128];
__device__ __align__(16) float g_mx  [2097152];
__device__ __align__(16) float g_mn  [2097152];
__device__ __align__(16) float g_cent[2097152];
__device__ __align__(16) unsigned g_Whi[98304];
__device__ __align__(16) unsigned g_Wlo[98304];
__device__ int    g_fps1[BB*SA];
__device__ int    g_fps2[BB*SBp];
__device__ int    g_knn1[BB*SA*KNB];
__device__ int    g_knn2[BB*SBp*KNB];
__device__ double g_dsum[256];
__device__ double g_dsq [256];
__device__ __align__(16) float g_scale[256];
__device__ __align__(16) float g_shift[256];

// weight-split offsets (uint32 units)
#define OW2  0
#define O11L 2048
#define O11D 6144
#define O12  10240
#define O21L 18432
#define O21D 34816
#define O22  51200

// ---------------- small helpers ----------------
__device__ __forceinline__ float d2_nofma(float ax,float ay,float az,float bx,float by,float bz){
    float dx = ax - bx, dy = ay - by, dz = az - bz;
    return __fadd_rn(__fadd_rn(__fmul_rn(dx,dx), __fmul_rn(dy,dy)), __fmul_rn(dz,dz));
}

// split two floats into packed bf16x2 hi and lo (3-term compensation)
__device__ __forceinline__ void split2(float x, float y, unsigned &uh, unsigned &ul){
    asm("cvt.rn.bf16x2.f32 %0, %1, %2;" : "=r"(uh) : "f"(y), "f"(x));
    float rx = x - __uint_as_float(uh << 16);
    float ry = y - __uint_as_float(uh & 0xFFFF0000u);
    asm("cvt.rn.bf16x2.f32 %0, %1, %2;" : "=r"(ul) : "f"(ry), "f"(rx));
}

// ---------------- weight pre-split ----------------
__global__ void k_prepW(const float* __restrict__ W, int off, int n2){
    int t = blockIdx.x*blockDim.x + threadIdx.x;
    if (t >= n2) return;
    unsigned h, l;
    split2(W[2*t], W[2*t+1], h, l);
    g_Whi[off+t] = h;
    g_Wlo[off+t] = l;
}

// split left half (cols [0,D/2)) and diff (right-left) of W[rows][D]
__global__ void k_prepHalf(const float* __restrict__ W, int D, int offL, int offD, int n2){
    int t = blockIdx.x*blockDim.x + threadIdx.x;
    if (t >= n2) return;
    int rw = D >> 2;
    int r = t / rw, c2 = t % rw;
    int base = r*D + 2*c2;
    float xl = W[base],        yl = W[base+1];
    float xr = W[base + D/2],  yr = W[base + D/2 + 1];
    unsigned h, l;
    split2(xl, yl, h, l);
    g_Whi[offL+t] = h; g_Wlo[offL+t] = l;
    split2(xr-xl, yr-yl, h, l);
    g_Whi[offD+t] = h; g_Wlo[offD+t] = l;
}

// ---------------- layout / stem ----------------
__global__ void k_xyzT(const float* __restrict__ x){
    int t = blockIdx.x*blockDim.x + threadIdx.x;
    if (t >= BB*NPTS) return;
    int b = t / NPTS, n = t % NPTS;
    g_xyz[t*3+0] = x[(b*3+0)*NPTS + n];
    g_xyz[t*3+1] = x[(b*3+1)*NPTS + n];
    g_xyz[t*3+2] = x[(b*3+2)*NPTS + n];
}

__global__ void k_stem1(const float* __restrict__ w1){
    int t = blockIdx.x*blockDim.x + threadIdx.x;
    if (t >= BB*NPTS*64) return;
    int c = t & 63, p = t >> 6;
    float X = g_xyz[p*3+0], Y = g_xyz[p*3+1], Z = g_xyz[p*3+2];
    g_bufA[t] = X*__ldg(&w1[c*3+0]) + Y*__ldg(&w1[c*3+1]) + Z*__ldg(&w1[c*3+2]);
}

__global__ void k_ew_f(){
    int t = blockIdx.x*blockDim.x + threadIdx.x;
    if (t >= BB*NPTS*64) return;
    int c = t & 63;
    g_f[t] = fmaxf(fmaf(g_bufB[t], g_scale[c], g_shift[c]), 0.f);
}

// ---------------- BN statistics (standalone pass: stem layer-1 only) ----------------
__global__ void k_zero(){
    int t = threadIdx.x;
    if (t < 256){ g_dsum[t] = 0.0; g_dsq[t] = 0.0; }
}

__global__ void k_stats(int sel, long long total, int C){
    const float* __restrict__ buf = sel ? g_bufB : g_bufA;
    int t = threadIdx.x;
    long long i      = (long long)blockIdx.x*256 + t;
    long long stride = (long long)gridDim.x*256;
    double S = 0.0, Q = 0.0;
    float s = 0.f, q = 0.f; int cnt = 0;
    for (; i < total; i += stride){
        float v = buf[i];
        s += v; q += v*v;
        if (++cnt == 64){ S += s; Q += q; s = 0.f; q = 0.f; cnt = 0; }
    }
    S += s; Q += q;
    __shared__ double shS[256], shQ[256];
    shS[t] = S; shQ[t] = Q; __syncthreads();
    if (t < C){
        double a = shS[t], b = shQ[t];
        for (int j = t + C; j < 256; j += C){ a += shS[j]; b += shQ[j]; }
        atomicAdd(&g_dsum[t], a);
        atomicAdd(&g_dsq [t], b);
    }
}

// reads stats, computes scale/shift, then ZEROES the accumulators for the next layer
__global__ void k_stats_final(const float* __restrict__ g, const float* __restrict__ b,
                              int C, double n){
    int c = threadIdx.x;
    if (c < 256){
        double sum = g_dsum[c], sq = g_dsq[c];
        if (c < C){
            double mean = sum / n;
            double var  = sq / n - mean*mean;
            double inv  = 1.0 / sqrt(var + 1e-5);
            float sc = g[c] * (float)inv;
            g_scale[c] = sc;
            g_shift[c] = b[c] - (float)mean * sc;
        }
        g_dsum[c] = 0.0;
        g_dsq [c] = 0.0;
    }
}

// ---------------- FPS (512 threads; 4 pts/thread at N=2048) ----------------
__global__ void __launch_bounds__(512) k_fps(int which){
    int b = blockIdx.x;
    const float* coords; int N, Sn; int* fidx; float* nxyz;
    if (which == 0){ coords = g_xyz;  N = NPTS; Sn = SA;  fidx = g_fps1; nxyz = g_xyz1; }
    else           { coords = g_xyz1; N = SA;   Sn = SBp; fidx = g_fps2; nxyz = g_xyz2; }

    __shared__ float sx[NPTS*3];
    __shared__ float rd[16];
    __shared__ int   ri[16];
    __shared__ int   sh_far;

    int t = threadIdx.x;
    const float* cb = coords + (size_t)b*N*3;
    for (int i = t; i < N*3; i += 512) sx[i] = cb[i];
    if (t == 0) sh_far = 0;
    float dist[4];
#pragma unroll
    for (int j = 0; j < 4; j++) dist[j] = 1e10f;
    int npt = N >> 9;
    __syncthreads();

    for (int it = 0; it < Sn; ++it){
        int far = sh_far;
        if (t == 0){
            fidx[b*Sn + it] = far;
            nxyz[((size_t)b*Sn + it)*3 + 0] = sx[far*3+0];
            nxyz[((size_t)b*Sn + it)*3 + 1] = sx[far*3+1];
            nxyz[((size_t)b*Sn + it)*3 + 2] = sx[far*3+2];
        }
        float cx = sx[far*3+0], cy = sx[far*3+1], cz = sx[far*3+2];
        float bd = -1.f; int bi = 0x7fffffff;
        for (int j = 0; j < npt; j++){
            int p = t + j*512;
            float d  = d2_nofma(sx[p*3+0], sx[p*3+1], sx[p*3+2], cx, cy, cz);
            float dj = fminf(dist[j], d);
            dist[j] = dj;
            if (dj > bd || (dj == bd && p < bi)){ bd = dj; bi = p; }
        }
#pragma unroll
        for (int off = 16; off; off >>= 1){
            float od = __shfl_down_sync(0xffffffffu, bd, off);
            int   oi = __shfl_down_sync(0xffffffffu, bi, off);
            if (od > bd || (od == bd && oi < bi)){ bd = od; bi = oi; }
        }
        if ((t & 31) == 0){ rd[t>>5] = bd; ri[t>>5] = bi; }
        __syncthreads();
        if (t < 32){
            bd = (t < 16) ? rd[t] : -1.f;
            bi = (t < 16) ? ri[t] : 0x7fffffff;
#pragma unroll
            for (int off = 8; off; off >>= 1){
                float od = __shfl_down_sync(0xffffffffu, bd, off);
                int   oi = __shfl_down_sync(0xffffffffu, bi, off);
                if (od > bd || (od == bd && oi < bi)){ bd = od; bi = oi; }
            }
            if (t == 0) sh_far = bi;
        }
        __syncthreads();
    }
}

// ---------------- kNN ----------------
__device__ __forceinline__ bool heap_gt(float d1, int i1, float d2, int i2){
    return (d1 > d2) || (d1 == d2 && i1 > i2);
}
__device__ __forceinline__ void sift_down(float* hd, int* hi, int i){
    for (;;){
        int l = 2*i+1, r = 2*i+2, m = i;
        if (l < 32 && heap_gt(hd[l], hi[l], hd[m], hi[m])) m = l;
        if (r < 32 && heap_gt(hd[r], hi[r], hd[m], hi[m])) m = r;
        if (m == i) break;
        float td = hd[i]; hd[i] = hd[m]; hd[m] = td;
        int   ti = hi[i]; hi[i] = hi[m]; hi[m] = ti;
        i = m;
    }
}

__global__ void __launch_bounds__(128) k_knn(int which){
    int b = blockIdx.x;
    const float* coords; const float* centers; int N, Sn; int* knn;
    if (which == 0){ coords = g_xyz;  centers = g_xyz1; N = NPTS; Sn = SA;  knn = g_knn1; }
    else           { coords = g_xyz1; centers = g_xyz2; N = SA;   Sn = SBp; knn = g_knn2; }

    __shared__ float sx[NPTS*3];
    const float* cb = coords + (size_t)b*N*3;
    for (int i = threadIdx.x; i < N*3; i += 128) sx[i] = cb[i];
    __syncthreads();

    int s = blockIdx.y*128 + threadIdx.x;
    const float* cp = centers + ((size_t)b*Sn + s)*3;
    float cx = cp[0], cy = cp[1], cz = cp[2];

    float hd[32]; int hi[32];
#pragma unroll
    for (int n = 0; n < 32; n++){
        hd[n] = d2_nofma(sx[n*3+0], sx[n*3+1], sx[n*3+2], cx, cy, cz);
        hi[n] = n;
    }
    for (int i = 15; i >= 0; --i) sift_down(hd, hi, i);
    for (int n = 32; n < N; n++){
        float d = d2_nofma(sx[n*3+0], sx[n*3+1], sx[n*3+2], cx, cy, cz);
        if (d < hd[0]){ hd[0] = d; hi[0] = n; sift_down(hd, hi, 0); }
    }
    int* o = knn + ((size_t)b*Sn + s)*32;
#pragma unroll
    for (int i = 0; i < 32; i++) o[i] = hi[i];
}

// ---------------- split-bf16 x3 GEMM, interleaved-permuted smem (uint4 fragment loads) ----------
// Layout: per tile row (128 rows, stride RSU=44 u32): for k-chunk of 32 (16 bf16x2 words),
// word W (0..15) stored at  (W>>3)*16 + p(W&7)*2  with p(w) = (w&3)*2 + (w>>2),
// hi plane at +0, lo plane at +1.  Fragment load = one uint4 per (row, k8):
// (a0h, a0l, a2h, a2l) at row*44 + k8*16 + tid4*4.
// MODE: 1 A=relu(bn(In)); 2/3 neighbor gather (g_f / g_f1) + cent epilogue; 4/5 center gather.
// MM: 1 = minmax epilogue (no Out). ST: 1 = fused BN-stats.
#define RSU   44                 // u32 row stride
#define TILEU (128*RSU)          // u32 per tile
#define DSMEM_B (4*TILEU*4)      // A+B tiles x 2 buffers = 90112 bytes

template<int NF, int MODE, int MM, int ST>
__global__ void __launch_bounds__(256) k_mma(int inSel, int woff,
                                             int outSel, int D, int COUT){
    const float* __restrict__ In  = inSel  ? g_bufB : g_bufA;
    float* __restrict__       Out = (outSel == 2) ? g_cent : (outSel ? g_bufB : g_bufA);
    const unsigned* __restrict__ Wh = g_Whi + woff;
    const unsigned* __restrict__ Wl = g_Wlo + woff;

    extern __shared__ unsigned dynsm[];
    __shared__ int   shIx[128];
    __shared__ float shSum[128], shSq[128];

    const int t    = threadIdx.x;
    const int lane = t & 31;
    const int wid  = t >> 5;
    const int g    = lane >> 2;
    const int tid4 = lane & 3;
    const int wr   = wid >> 2;
    const int wc   = wid & 3;
    const int m0   = blockIdx.x * 128;
    const int c0   = blockIdx.y * (NF*32);
    const int CTILE = NF*32;

    if (t < 128){ shSum[t] = 0.f; shSq[t] = 0.f; }
    if (MODE >= 2 && t < 128){
        int m = m0 + t;
        if (MODE == 2){
            int b = m >> 14;
            shIx[t] = b*NPTS*16 + g_knn1[m]*16;
        } else if (MODE == 3){
            int b = m >> 13;
            shIx[t] = b*SA*32 + g_knn2[m]*32;
        } else if (MODE == 4){
            int b = m >> 9;
            shIx[t] = b*NPTS*16 + g_fps1[m]*16;
        } else {
            int b = m >> 8;
            shIx[t] = b*SA*32 + g_fps2[m]*32;
        }
    }
    if (MODE >= 2) __syncthreads();

    float acc[4][NF][4];
#pragma unroll
    for (int i = 0; i < 4; i++)
#pragma unroll
        for (int j = 0; j < NF; j++)
#pragma unroll
            for (int q = 0; q < 4; q++) acc[i][j][q] = 0.f;

    const float4* f4src = (MODE == 2 || MODE == 4) ? (const float4*)g_f : (const float4*)g_f1;
    const int Dq  = D >> 1;
    const int BPASS = (CTILE == 128) ? 4 : 2;

    // stage one 32-wide K chunk into buffer 'buf' (A then B tile)
    auto stage = [&](int kc, int buf){
        unsigned* dA = dynsm + buf*2*TILEU;
        unsigned* dB = dA + TILEU;
#pragma unroll
        for (int p = 0; p < 4; p++){
            int idx = t + p*256;
            int r = idx >> 3, c4 = idx & 7;
            float4 v;
            if (MODE >= 2){
                v = f4src[shIx[r] + (kc >> 2) + c4];
            } else {
                v = *(const float4*)&In[(size_t)(m0+r)*D + kc + c4*4];
                if (MODE == 1){
                    float4 sc = *(const float4*)&g_scale[kc + c4*4];
                    float4 sf = *(const float4*)&g_shift[kc + c4*4];
                    v.x = fmaxf(fmaf(v.x, sc.x, sf.x), 0.f);
                    v.y = fmaxf(fmaf(v.y, sc.y, sf.y), 0.f);
                    v.z = fmaxf(fmaf(v.z, sc.z, sf.z), 0.f);
                    v.w = fmaxf(fmaf(v.w, sc.w, sf.w), 0.f);
                }
            }
            unsigned h0,l0,h1,l1;
            split2(v.x, v.y, h0, l0);
            split2(v.z, v.w, h1, l1);
            int W0 = c4*2, W1 = W0+1;
            int o0 = (W0 & 8)*2 + (((W0&3)*2 + ((W0>>2)&1)) * 2);
            int o1 = (W1 & 8)*2 + (((W1&3)*2 + ((W1>>2)&1)) * 2);
            *(uint2*)&dA[r*RSU + o0] = make_uint2(h0, l0);
            *(uint2*)&dA[r*RSU + o1] = make_uint2(h1, l1);
        }
#pragma unroll
        for (int p = 0; p < 4; p++){
            if (p >= BPASS) break;
            int idx = t + p*256;
            int r = idx >> 3, c4 = idx & 7;
            size_t gi = (size_t)(c0+r)*Dq + (kc>>1) + c4*2;
            uint2 hv = *(const uint2*)&Wh[gi];
            uint2 lv = *(const uint2*)&Wl[gi];
            int W0 = c4*2, W1 = W0+1;
            int o0 = (W0 & 8)*2 + (((W0&3)*2 + ((W0>>2)&1)) * 2);
            int o1 = (W1 & 8)*2 + (((W1&3)*2 + ((W1>>2)&1)) * 2);
            *(uint2*)&dB[r*RSU + o0] = make_uint2(hv.x, lv.x);
            *(uint2*)&dB[r*RSU + o1] = make_uint2(hv.y, lv.y);
        }
    };

    const int NC = D >> 5;
    stage(0, 0);
    __syncthreads();

    for (int c = 0; c < NC; c++){
        int cur = c & 1;
        if (c + 1 < NC) stage((c+1)*32, 1 - cur);

        const unsigned* cA = dynsm + cur*2*TILEU;
        const unsigned* cB = cA + TILEU;

#pragma unroll
        for (int k8 = 0; k8 < 2; k8++){
            const int ko = k8*16 + tid4*4;
            unsigned ah[4][4], al[4][4];
#pragma unroll
            for (int mf = 0; mf < 4; mf++){
                int ra = (wr*64 + mf*16 + g)*RSU + ko;
                uint4 u0 = *(const uint4*)&cA[ra];
                uint4 u1 = *(const uint4*)&cA[ra + 8*RSU];
                ah[mf][0] = u0.x; al[mf][0] = u0.y;
                ah[mf][2] = u0.z; al[mf][2] = u0.w;
                ah[mf][1] = u1.x; al[mf][1] = u1.y;
                ah[mf][3] = u1.z; al[mf][3] = u1.w;
            }
#pragma unroll
            for (int nf = 0; nf < NF; nf++){
                int ib = (wc*NF*8 + nf*8 + g)*RSU + ko;
                uint4 ub = *(const uint4*)&cB[ib];
                unsigned bh0 = ub.x, bl0 = ub.y, bh1 = ub.z, bl1 = ub.w;
#pragma unroll
                for (int mf = 0; mf < 4; mf++){
                    asm volatile(
                        "mma.sync.aligned.m16n8k16.row.col.f32.bf16.bf16.f32 "
                        "{%0,%1,%2,%3}, {%4,%5,%6,%7}, {%8,%9}, {%0,%1,%2,%3};"
                        : "+f"(acc[mf][nf][0]), "+f"(acc[mf][nf][1]),
                          "+f"(acc[mf][nf][2]), "+f"(acc[mf][nf][3])
                        : "r"(ah[mf][0]), "r"(ah[mf][1]), "r"(ah[mf][2]), "r"(ah[mf][3]),
                          "r"(bl0), "r"(bl1));
                    asm volatile(
                        "mma.sync.aligned.m16n8k16.row.col.f32.bf16.bf16.f32 "
                        "{%0,%1,%2,%3}, {%4,%5,%6,%7}, {%8,%9}, {%0,%1,%2,%3};"
                        : "+f"(acc[mf][nf][0]), "+f"(acc[mf][nf][1]),
                          "+f"(acc[mf][nf][2]), "+f"(acc[mf][nf][3])
                        : "r"(al[mf][0]), "r"(al[mf][1]), "r"(al[mf][2]), "r"(al[mf][3]),
                          "r"(bh0), "r"(bh1));
                    asm volatile(
                        "mma.sync.aligned.m16n8k16.row.col.f32.bf16.bf16.f32 "
                        "{%0,%1,%2,%3}, {%4,%5,%6,%7}, {%8,%9}, {%0,%1,%2,%3};"
                        : "+f"(acc[mf][nf][0]), "+f"(acc[mf][nf][1]),
                          "+f"(acc[mf][nf][2]), "+f"(acc[mf][nf][3])
                        : "r"(ah[mf][0]), "r"(ah[mf][1]), "r"(ah[mf][2]), "r"(ah[mf][3]),
                          "r"(bh0), "r"(bh1));
                }
            }
        }
        __syncthreads();
    }

    // ---- add per-center contribution (neighbor GEMMs only) ----
    if (MODE == 2 || MODE == 3){
#pragma unroll
        for (int mf = 0; mf < 4; mf++){
            int bsg = (m0 + wr*64 + mf*16) >> 5;
#pragma unroll
            for (int nf = 0; nf < NF; nf++){
                int col = c0 + wc*NF*8 + nf*8 + tid4*2;
                float2 cv = *(const float2*)&g_cent[(size_t)bsg*COUT + col];
                acc[mf][nf][0] += cv.x; acc[mf][nf][1] += cv.y;
                acc[mf][nf][2] += cv.x; acc[mf][nf][3] += cv.y;
            }
        }
    }

    // ---- epilogue: Out write OR fused per-group max/min ----
    if (!MM){
#pragma unroll
        for (int mf = 0; mf < 4; mf++){
            int row0 = m0 + wr*64 + mf*16 + g;
#pragma unroll
            for (int nf = 0; nf < NF; nf++){
                int col = c0 + wc*NF*8 + nf*8 + tid4*2;
                *(float2*)&Out[(size_t)row0*COUT + col]     = make_float2(acc[mf][nf][0], acc[mf][nf][1]);
                *(float2*)&Out[(size_t)(row0+8)*COUT + col] = make_float2(acc[mf][nf][2], acc[mf][nf][3]);
            }
        }
    } else {
#pragma unroll
        for (int gi = 0; gi < 2; gi++){
#pragma unroll
            for (int nf = 0; nf < NF; nf++){
#pragma unroll
                for (int j = 0; j < 2; j++){
                    float mx = fmaxf(fmaxf(acc[2*gi][nf][j],   acc[2*gi][nf][j+2]),
                                     fmaxf(acc[2*gi+1][nf][j], acc[2*gi+1][nf][j+2]));
                    float mn = fminf(fminf(acc[2*gi][nf][j],   acc[2*gi][nf][j+2]),
                                     fminf(acc[2*gi+1][nf][j], acc[2*gi+1][nf][j+2]));
#pragma unroll
                    for (int off = 4; off <= 16; off <<= 1){
                        mx = fmaxf(mx, __shfl_xor_sync(0xffffffffu, mx, off));
                        mn = fminf(mn, __shfl_xor_sync(0xffffffffu, mn, off));
                    }
                    if (lane < 4){
                        int col = c0 + wc*NF*8 + nf*8 + tid4*2 + j;
                        int bsg = (m0 >> 5) + wr*2 + gi;
                        g_mx[(size_t)bsg*COUT + col] = mx;
                        g_mn[(size_t)bsg*COUT + col] = mn;
                    }
                }
            }
        }
    }

    // ---- fused BN-stats (only when ST) ----
    if (ST){
        float cs[NF][2], cq[NF][2];
#pragma unroll
        for (int nf = 0; nf < NF; nf++){
            cs[nf][0] = cs[nf][1] = 0.f;
            cq[nf][0] = cq[nf][1] = 0.f;
        }
#pragma unroll
        for (int mf = 0; mf < 4; mf++){
#pragma unroll
            for (int nf = 0; nf < NF; nf++){
                float a0 = acc[mf][nf][0], a1 = acc[mf][nf][1];
                float a2 = acc[mf][nf][2], a3 = acc[mf][nf][3];
                cs[nf][0] += a0 + a2;         cs[nf][1] += a1 + a3;
                cq[nf][0] += a0*a0 + a2*a2;   cq[nf][1] += a1*a1 + a3*a3;
            }
        }
#pragma unroll
        for (int off = 4; off <= 16; off <<= 1){
#pragma unroll
            for (int nf = 0; nf < NF; nf++){
                cs[nf][0] += __shfl_xor_sync(0xffffffffu, cs[nf][0], off);
                cs[nf][1] += __shfl_xor_sync(0xffffffffu, cs[nf][1], off);
                cq[nf][0] += __shfl_xor_sync(0xffffffffu, cq[nf][0], off);
                cq[nf][1] += __shfl_xor_sync(0xffffffffu, cq[nf][1], off);
            }
        }
        if (lane < 4){
#pragma unroll
            for (int nf = 0; nf < NF; nf++){
                int cl = wc*NF*8 + nf*8 + tid4*2;
                atomicAdd(&shSum[cl],   cs[nf][0]);
                atomicAdd(&shSum[cl+1], cs[nf][1]);
                atomicAdd(&shSq [cl],   cq[nf][0]);
                atomicAdd(&shSq [cl+1], cq[nf][1]);
            }
        }
        __syncthreads();
        if (t < CTILE){
            atomicAdd(&g_dsum[c0+t], (double)shSum[t]);
            atomicAdd(&g_dsq [c0+t], (double)shSq [t]);
        }
    }
}

// ---------------- finalize BN+ReLU+max from per-group raw extrema ----------------
__global__ void k_bnmax1(){
    int t = blockIdx.x*blockDim.x + threadIdx.x;
    if (t >= BB*SA*128) return;
    int c = t & 127;
    float sc = g_scale[c], sf = g_shift[c];
    float a = fmaxf(fmaf(g_mx[t], sc, sf), 0.f);
    float b = fmaxf(fmaf(g_mn[t], sc, sf), 0.f);
    g_f1[t] = fmaxf(a, b);
}

__global__ void k_bnmax2(float* __restrict__ out){
    int t = blockIdx.x*blockDim.x + threadIdx.x;
    if (t >= BB*SBp*256) return;
    int c = t & 255, bs = t >> 8;
    int b = bs >> 8, s = bs & 255;
    float sc = g_scale[c], sf = g_shift[c];
    float a  = fmaxf(fmaf(g_mx[t], sc, sf), 0.f);
    float b2 = fmaxf(fmaf(g_mn[t], sc, sf), 0.f);
    out[(size_t)b*65536 + c*256 + s] = fmaxf(a, b2);
}

// ---------------- launch ----------------
extern "C" void kernel_launch(void* const* d_in, const int* in_sizes, int n_in,
                              void* d_out, int out_size){
    (void)in_sizes; (void)n_in; (void)out_size;
    const float* x    = (const float*)d_in[0];
    const float* w1   = (const float*)d_in[1];
    const float* g1   = (const float*)d_in[2];
    const float* b1   = (const float*)d_in[3];
    const float* w2   = (const float*)d_in[4];
    const float* g2   = (const float*)d_in[5];
    const float* b2   = (const float*)d_in[6];
    const float* s1w1 = (const float*)d_in[7];
    const float* s1g1 = (const float*)d_in[8];
    const float* s1b1 = (const float*)d_in[9];
    const float* s1w2 = (const float*)d_in[10];
    const float* s1g2 = (const float*)d_in[11];
    const float* s1b2 = (const float*)d_in[12];
    const float* s2w1 = (const float*)d_in[13];
    const float* s2g1 = (const float*)d_in[14];
    const float* s2b1 = (const float*)d_in[15];
    const float* s2w2 = (const float*)d_in[16];
    const float* s2g2 = (const float*)d_in[17];
    const float* s2b2 = (const float*)d_in[18];
    float* out = (float*)d_out;

    cudaFuncSetAttribute(k_mma<2,1,0,1>, cudaFuncAttributeMaxDynamicSharedMemorySize, DSMEM_B);
    cudaFuncSetAttribute(k_mma<4,2,0,1>, cudaFuncAttributeMaxDynamicSharedMemorySize, DSMEM_B);
    cudaFuncSetAttribute(k_mma<4,3,0,1>, cudaFuncAttributeMaxDynamicSharedMemorySize, DSMEM_B);
    cudaFuncSetAttribute(k_mma<4,1,1,1>, cudaFuncAttributeMaxDynamicSharedMemorySize, DSMEM_B);
    cudaFuncSetAttribute(k_mma<4,4,0,0>, cudaFuncAttributeMaxDynamicSharedMemorySize, DSMEM_B);
    cudaFuncSetAttribute(k_mma<4,5,0,0>, cudaFuncAttributeMaxDynamicSharedMemorySize, DSMEM_B);

    k_xyzT    <<<256, 256>>>(x);
    k_prepW   <<<8,  256>>>(w2,   OW2, 2048);
    k_fps     <<<32, 512>>>(0);
    k_knn     <<<dim3(32,4), 128>>>(0);
    k_prepHalf<<<16, 256>>>(s1w1, 128, O11L, O11D, 4096);
    k_prepW   <<<32, 256>>>(s1w2, O12, 8192);
    k_prepHalf<<<64, 256>>>(s2w1, 256, O21L, O21D, 16384);
    k_prepW   <<<128,256>>>(s2w2, O22, 32768);
    k_zero    <<<1,  256>>>();
    k_fps     <<<32, 512>>>(1);
    k_knn     <<<dim3(32,2), 128>>>(1);

    // ---- stem ----
    k_stem1<<<16384, 256>>>(w1);
    k_stats<<<512,256>>>(0, (long long)65536*64, 64);
    k_stats_final<<<1,256>>>(g1, b1, 64, 65536.0);
    k_mma<2,1,0,1><<<dim3(512,1),256,DSMEM_B>>>(0, OW2, 1, 64, 64);
    k_stats_final<<<1,256>>>(g2, b2, 64, 65536.0);
    k_ew_f<<<16384,256>>>();

    // ---- SG1 ----
    k_mma<4,4,0,0><<<dim3(128,1),256,DSMEM_B>>>(0, O11D, 2, 64, 128);    // centers
    k_mma<4,2,0,1><<<dim3(4096,1),256,DSMEM_B>>>(0, O11L, 0, 64, 128);   // nbrs + cent (+stats)
    k_stats_final<<<1,256>>>(s1g1, s1b1, 128, 524288.0);
    k_mma<4,1,1,1><<<dim3(4096,1),256,DSMEM_B>>>(0, O12, 1, 128, 128);   // GEMM2 -> minmax (+stats)
    k_stats_final<<<1,256>>>(s1g2, s1b2, 128, 524288.0);
    k_bnmax1<<<8192,256>>>();

    // ---- SG2 ----
    k_mma<4,5,0,0><<<dim3(64,2),256,DSMEM_B>>>(0, O21D, 2, 128, 256);    // centers
    k_mma<4,3,0,1><<<dim3(2048,2),256,DSMEM_B>>>(0, O21L, 0, 128, 256);  // nbrs + cent (+stats)
    k_stats_final<<<1,256>>>(s2g1, s2b1, 256, 262144.0);
    k_mma<4,1,1,1><<<dim3(2048,2),256,DSMEM_B>>>(0, O22, 1, 256, 256);   // GEMM2 -> minmax (+stats)
    k_stats_final<<<1,256>>>(s2g2, s2b2, 256, 262144.0);
    k_bnmax2<<<8192,256>>>(out);
}

// round 17
// speedup vs baseline: 1.0568x; 1.0568x over previous
#include <cuda_runtime.h>
#include <cuda_bf16.h>
#include <cstdint>
#include <math.h>

#define BB   32
#define NPTS 2048
#define SA   512
#define SBp  256
#define KNB  32

// ---------------- scratch (device globals; no allocations allowed) ----------------
__device__ __align__(16) float g_bufA[67108864];   // 268MB
__device__ __align__(16) float g_bufB[67108864];   // 268MB
__device__ __align__(16) float g_xyz [BB*NPTS*3];
__device__ __align__(16) float g_f   [BB*NPTS*64];
__device__ __align__(16) float g_xyz1[BB*SA*3];
__device__ __align__(16) float g_xyz2[BB*SBp*3];
__device__ __align__(16) float g_f1  [BB*SA*128];
__device__ __align__(16) float g_mx  [2097152];
__device__ __align__(16) float g_mn  [2097152];
__device__ __align__(16) float g_cent[2097152];
__device__ __align__(16) unsigned g_Whi[98304];
__device__ __align__(16) unsigned g_Wlo[98304];
__device__ int    g_fps1[BB*SA];
__device__ int    g_fps2[BB*SBp];
__device__ int    g_knn1[BB*SA*KNB];
__device__ int    g_knn2[BB*SBp*KNB];
__device__ double g_dsum[256];
__device__ double g_dsq [256];
__device__ __align__(16) float g_scale[256];
__device__ __align__(16) float g_shift[256];

// weight-split offsets (uint32 units)
#define OW2  0
#define O11L 2048
#define O11D 6144
#define O12  10240
#define O21L 18432
#define O21D 34816
#define O22  51200

// ---------------- small helpers ----------------
__device__ __forceinline__ float d2_nofma(float ax,float ay,float az,float bx,float by,float bz){
    float dx = ax - bx, dy = ay - by, dz = az - bz;
    return __fadd_rn(__fadd_rn(__fmul_rn(dx,dx), __fmul_rn(dy,dy)), __fmul_rn(dz,dz));
}

// split two floats into packed bf16x2 hi and lo (3-term compensation)
__device__ __forceinline__ void split2(float x, float y, unsigned &uh, unsigned &ul){
    asm("cvt.rn.bf16x2.f32 %0, %1, %2;" : "=r"(uh) : "f"(y), "f"(x));
    float rx = x - __uint_as_float(uh << 16);
    float ry = y - __uint_as_float(uh & 0xFFFF0000u);
    asm("cvt.rn.bf16x2.f32 %0, %1, %2;" : "=r"(ul) : "f"(ry), "f"(rx));
}

// ---------------- weight pre-split ----------------
__global__ void k_prepW(const float* __restrict__ W, int off, int n2){
    int t = blockIdx.x*blockDim.x + threadIdx.x;
    if (t >= n2) return;
    unsigned h, l;
    split2(W[2*t], W[2*t+1], h, l);
    g_Whi[off+t] = h;
    g_Wlo[off+t] = l;
}

// split left half (cols [0,D/2)) and diff (right-left) of W[rows][D]
__global__ void k_prepHalf(const float* __restrict__ W, int D, int offL, int offD, int n2){
    int t = blockIdx.x*blockDim.x + threadIdx.x;
    if (t >= n2) return;
    int rw = D >> 2;
    int r = t / rw, c2 = t % rw;
    int base = r*D + 2*c2;
    float xl = W[base],        yl = W[base+1];
    float xr = W[base + D/2],  yr = W[base + D/2 + 1];
    unsigned h, l;
    split2(xl, yl, h, l);
    g_Whi[offL+t] = h; g_Wlo[offL+t] = l;
    split2(xr-xl, yr-yl, h, l);
    g_Whi[offD+t] = h; g_Wlo[offD+t] = l;
}

// ---------------- layout / stem ----------------
__global__ void k_xyzT(const float* __restrict__ x){
    int t = blockIdx.x*blockDim.x + threadIdx.x;
    if (t >= BB*NPTS) return;
    int b = t / NPTS, n = t % NPTS;
    g_xyz[t*3+0] = x[(b*3+0)*NPTS + n];
    g_xyz[t*3+1] = x[(b*3+1)*NPTS + n];
    g_xyz[t*3+2] = x[(b*3+2)*NPTS + n];
}

// stem layer-1 with FUSED BN-stats: grid-stride over B*N*64, per-thread compensated
// partials (same cadence as the old k_stats), block-reduce, one atomic per channel.
__global__ void __launch_bounds__(256) k_stem1(const float* __restrict__ w1){
    const long long total = (long long)BB*NPTS*64;
    int t = threadIdx.x;
    long long i      = (long long)blockIdx.x*256 + t;
    long long stride = (long long)gridDim.x*256;     // multiple of 64
    double S = 0.0, Q = 0.0;
    float s = 0.f, q = 0.f; int cnt = 0;
    int c = (int)(i & 63);
    float wx = __ldg(&w1[c*3+0]), wy = __ldg(&w1[c*3+1]), wz = __ldg(&w1[c*3+2]);
    for (; i < total; i += stride){
        long long p = i >> 6;
        float v = g_xyz[p*3+0]*wx + g_xyz[p*3+1]*wy + g_xyz[p*3+2]*wz;
        g_bufA[i] = v;
        s += v; q += v*v;
        if (++cnt == 64){ S += s; Q += q; s = 0.f; q = 0.f; cnt = 0; }
    }
    S += s; Q += q;
    __shared__ double shS[256], shQ[256];
    shS[t] = S; shQ[t] = Q; __syncthreads();
    if (t < 64){
        double a = shS[t] + shS[t+64] + shS[t+128] + shS[t+192];
        double b = shQ[t] + shQ[t+64] + shQ[t+128] + shQ[t+192];
        atomicAdd(&g_dsum[t], a);
        atomicAdd(&g_dsq [t], b);
    }
}

__global__ void k_ew_f(){
    int t = blockIdx.x*blockDim.x + threadIdx.x;
    if (t >= BB*NPTS*64) return;
    int c = t & 63;
    g_f[t] = fmaxf(fmaf(g_bufB[t], g_scale[c], g_shift[c]), 0.f);
}

// ---------------- BN statistics ----------------
__global__ void k_zero(){
    int t = threadIdx.x;
    if (t < 256){ g_dsum[t] = 0.0; g_dsq[t] = 0.0; }
}

// reads stats, computes scale/shift, then ZEROES the accumulators for the next layer
__global__ void k_stats_final(const float* __restrict__ g, const float* __restrict__ b,
                              int C, double n){
    int c = threadIdx.x;
    if (c < 256){
        double sum = g_dsum[c], sq = g_dsq[c];
        if (c < C){
            double mean = sum / n;
            double var  = sq / n - mean*mean;
            double inv  = 1.0 / sqrt(var + 1e-5);
            float sc = g[c] * (float)inv;
            g_scale[c] = sc;
            g_shift[c] = b[c] - (float)mean * sc;
        }
        g_dsum[c] = 0.0;
        g_dsq [c] = 0.0;
    }
}

// ---------------- FPS (512 threads; 4 pts/thread at N=2048) ----------------
__global__ void __launch_bounds__(512) k_fps(int which){
    int b = blockIdx.x;
    const float* coords; int N, Sn; int* fidx; float* nxyz;
    if (which == 0){ coords = g_xyz;  N = NPTS; Sn = SA;  fidx = g_fps1; nxyz = g_xyz1; }
    else           { coords = g_xyz1; N = SA;   Sn = SBp; fidx = g_fps2; nxyz = g_xyz2; }

    __shared__ float sx[NPTS*3];
    __shared__ float rd[16];
    __shared__ int   ri[16];
    __shared__ int   sh_far;

    int t = threadIdx.x;
    const float* cb = coords + (size_t)b*N*3;
    for (int i = t; i < N*3; i += 512) sx[i] = cb[i];
    if (t == 0) sh_far = 0;
    float dist[4];
#pragma unroll
    for (int j = 0; j < 4; j++) dist[j] = 1e10f;
    int npt = N >> 9;
    __syncthreads();

    for (int it = 0; it < Sn; ++it){
        int far = sh_far;
        if (t == 0){
            fidx[b*Sn + it] = far;
            nxyz[((size_t)b*Sn + it)*3 + 0] = sx[far*3+0];
            nxyz[((size_t)b*Sn + it)*3 + 1] = sx[far*3+1];
            nxyz[((size_t)b*Sn + it)*3 + 2] = sx[far*3+2];
        }
        float cx = sx[far*3+0], cy = sx[far*3+1], cz = sx[far*3+2];
        float bd = -1.f; int bi = 0x7fffffff;
        for (int j = 0; j < npt; j++){
            int p = t + j*512;
            float d  = d2_nofma(sx[p*3+0], sx[p*3+1], sx[p*3+2], cx, cy, cz);
            float dj = fminf(dist[j], d);
            dist[j] = dj;
            if (dj > bd || (dj == bd && p < bi)){ bd = dj; bi = p; }
        }
#pragma unroll
        for (int off = 16; off; off >>= 1){
            float od = __shfl_down_sync(0xffffffffu, bd, off);
            int   oi = __shfl_down_sync(0xffffffffu, bi, off);
            if (od > bd || (od == bd && oi < bi)){ bd = od; bi = oi; }
        }
        if ((t & 31) == 0){ rd[t>>5] = bd; ri[t>>5] = bi; }
        __syncthreads();
        if (t < 32){
            bd = (t < 16) ? rd[t] : -1.f;
            bi = (t < 16) ? ri[t] : 0x7fffffff;
#pragma unroll
            for (int off = 8; off; off >>= 1){
                float od = __shfl_down_sync(0xffffffffu, bd, off);
                int   oi = __shfl_down_sync(0xffffffffu, bi, off);
                if (od > bd || (od == bd && oi < bi)){ bd = od; bi = oi; }
            }
            if (t == 0) sh_far = bi;
        }
        __syncthreads();
    }
}

// ---------------- kNN ----------------
__device__ __forceinline__ bool heap_gt(float d1, int i1, float d2, int i2){
    return (d1 > d2) || (d1 == d2 && i1 > i2);
}
__device__ __forceinline__ void sift_down(float* hd, int* hi, int i){
    for (;;){
        int l = 2*i+1, r = 2*i+2, m = i;
        if (l < 32 && heap_gt(hd[l], hi[l], hd[m], hi[m])) m = l;
        if (r < 32 && heap_gt(hd[r], hi[r], hd[m], hi[m])) m = r;
        if (m == i) break;
        float td = hd[i]; hd[i] = hd[m]; hd[m] = td;
        int   ti = hi[i]; hi[i] = hi[m]; hi[m] = ti;
        i = m;
    }
}

__global__ void __launch_bounds__(128) k_knn(int which){
    int b = blockIdx.x;
    const float* coords; const float* centers; int N, Sn; int* knn;
    if (which == 0){ coords = g_xyz;  centers = g_xyz1; N = NPTS; Sn = SA;  knn = g_knn1; }
    else           { coords = g_xyz1; centers = g_xyz2; N = SA;   Sn = SBp; knn = g_knn2; }

    __shared__ float sx[NPTS*3];
    const float* cb = coords + (size_t)b*N*3;
    for (int i = threadIdx.x; i < N*3; i += 128) sx[i] = cb[i];
    __syncthreads();

    int s = blockIdx.y*128 + threadIdx.x;
    const float* cp = centers + ((size_t)b*Sn + s)*3;
    float cx = cp[0], cy = cp[1], cz = cp[2];

    float hd[32]; int hi[32];
#pragma unroll
    for (int n = 0; n < 32; n++){
        hd[n] = d2_nofma(sx[n*3+0], sx[n*3+1], sx[n*3+2], cx, cy, cz);
        hi[n] = n;
    }
    for (int i = 15; i >= 0; --i) sift_down(hd, hi, i);
    for (int n = 32; n < N; n++){
        float d = d2_nofma(sx[n*3+0], sx[n*3+1], sx[n*3+2], cx, cy, cz);
        if (d < hd[0]){ hd[0] = d; hi[0] = n; sift_down(hd, hi, 0); }
    }
    int* o = knn + ((size_t)b*Sn + s)*32;
#pragma unroll
    for (int i = 0; i < 32; i++) o[i] = hi[i];
}

// ---------------- split-bf16 x3 tensor-core GEMM, K-pipelined double buffer (R12) ----------------
// Out[M,COUT] = A[M,D] @ W[COUT,D]^T, hi/lo bf16 split (3 MMA terms), W pre-split at woff.
// MODE: 0 plain A; 1 A=relu(bn(In));
//       2 A = gathered NEIGHBOR rows of g_f  (D=64),  epilogue adds g_cent[bs]
//       3 A = gathered NEIGHBOR rows of g_f1 (D=128), epilogue adds g_cent[bs]
//       4 A = gathered CENTER  rows of g_f  via fps1 (D=64)
//       5 A = gathered CENTER  rows of g_f1 via fps2 (D=128)
// MM: 1 = skip Out write; emit per-32-row-group raw max/min to g_mx/g_mn.
// ST: 1 = accumulate per-channel sum/sumsq into g_dsum/g_dsq.
#define RS32 20                 // smem row stride in uint32
#define BUFU (128*RS32)         // u32 per tile buffer
#define DSMEM_B (8*BUFU*4)      // 2 buffers x 4 arrays = 81920 bytes

template<int NF, int MODE, int MM, int ST>
__global__ void __launch_bounds__(256) k_mma(int inSel, int woff,
                                             int outSel, int D, int COUT){
    const float* __restrict__ In  = inSel  ? g_bufB : g_bufA;
    float* __restrict__       Out = (outSel == 2) ? g_cent : (outSel ? g_bufB : g_bufA);
    const unsigned* __restrict__ Wh = g_Whi + woff;
    const unsigned* __restrict__ Wl = g_Wlo + woff;

    extern __shared__ unsigned dynsm[];
    unsigned* sAhi = dynsm;
    unsigned* sAlo = dynsm + 2*BUFU;
    unsigned* sBhi = dynsm + 4*BUFU;
    unsigned* sBlo = dynsm + 6*BUFU;
    __shared__ int   shIx[128];
    __shared__ float shSum[128], shSq[128];

    const int t    = threadIdx.x;
    const int lane = t & 31;
    const int wid  = t >> 5;
    const int g    = lane >> 2;
    const int tid4 = lane & 3;
    const int wr   = wid >> 2;
    const int wc   = wid & 3;
    const int m0   = blockIdx.x * 128;
    const int c0   = blockIdx.y * (NF*32);
    const int CTILE = NF*32;

    if (t < 128){ shSum[t] = 0.f; shSq[t] = 0.f; }
    if (MODE >= 2 && t < 128){
        int m = m0 + t;
        if (MODE == 2){
            int b = m >> 14;
            shIx[t] = b*NPTS*16 + g_knn1[m]*16;
        } else if (MODE == 3){
            int b = m >> 13;
            shIx[t] = b*SA*32 + g_knn2[m]*32;
        } else if (MODE == 4){
            int b = m >> 9;
            shIx[t] = b*NPTS*16 + g_fps1[m]*16;
        } else {
            int b = m >> 8;
            shIx[t] = b*SA*32 + g_fps2[m]*32;
        }
    }
    if (MODE >= 2) __syncthreads();

    float acc[4][NF][4];
#pragma unroll
    for (int i = 0; i < 4; i++)
#pragma unroll
        for (int j = 0; j < NF; j++)
#pragma unroll
            for (int q = 0; q < 4; q++) acc[i][j][q] = 0.f;

    const float4* f4src = (MODE == 2 || MODE == 4) ? (const float4*)g_f : (const float4*)g_f1;
    const int Dq  = D >> 1;
    const int BPASS = (CTILE == 128) ? 4 : 2;

    auto stage = [&](int kc, int buf){
        unsigned* dAh = sAhi + buf*BUFU;
        unsigned* dAl = sAlo + buf*BUFU;
        unsigned* dBh = sBhi + buf*BUFU;
        unsigned* dBl = sBlo + buf*BUFU;
#pragma unroll
        for (int p = 0; p < 4; p++){
            int idx = t + p*256;
            int r = idx >> 3, c4 = idx & 7;
            float4 v;
            if (MODE >= 2){
                v = f4src[shIx[r] + (kc >> 2) + c4];
            } else {
                v = *(const float4*)&In[(size_t)(m0+r)*D + kc + c4*4];
                if (MODE == 1){
                    float4 sc = *(const float4*)&g_scale[kc + c4*4];
                    float4 sf = *(const float4*)&g_shift[kc + c4*4];
                    v.x = fmaxf(fmaf(v.x, sc.x, sf.x), 0.f);
                    v.y = fmaxf(fmaf(v.y, sc.y, sf.y), 0.f);
                    v.z = fmaxf(fmaf(v.z, sc.z, sf.z), 0.f);
                    v.w = fmaxf(fmaf(v.w, sc.w, sf.w), 0.f);
                }
            }
            unsigned h0,l0,h1,l1;
            split2(v.x, v.y, h0, l0);
            split2(v.z, v.w, h1, l1);
            int base = r*RS32 + c4*2;
            dAh[base] = h0; dAh[base+1] = h1;
            dAl[base] = l0; dAl[base+1] = l1;
        }
#pragma unroll
        for (int p = 0; p < 4; p++){
            if (p >= BPASS) break;
            int idx = t + p*256;
            int r = idx >> 3, c4 = idx & 7;
            size_t gi = (size_t)(c0+r)*Dq + (kc>>1) + c4*2;
            uint2 hv = *(const uint2*)&Wh[gi];
            uint2 lv = *(const uint2*)&Wl[gi];
            int base = r*RS32 + c4*2;
            dBh[base] = hv.x; dBh[base+1] = hv.y;
            dBl[base] = lv.x; dBl[base+1] = lv.y;
        }
    };

    const int NC = D >> 5;
    stage(0, 0);
    __syncthreads();

    for (int c = 0; c < NC; c++){
        int cur = c & 1;
        if (c + 1 < NC) stage((c+1)*32, 1 - cur);

        const unsigned* cAh = sAhi + cur*BUFU;
        const unsigned* cAl = sAlo + cur*BUFU;
        const unsigned* cBh = sBhi + cur*BUFU;
        const unsigned* cBl = sBlo + cur*BUFU;

#pragma unroll
        for (int k8 = 0; k8 < 2; k8++){
            const int ko = k8*8;
            unsigned ah[4][4], al[4][4];
#pragma unroll
            for (int mf = 0; mf < 4; mf++){
                int r0 = (wr*64 + mf*16 + g)*RS32 + ko + tid4;
                int r1 = r0 + 8*RS32;
                ah[mf][0] = cAh[r0];   ah[mf][1] = cAh[r1];
                ah[mf][2] = cAh[r0+4]; ah[mf][3] = cAh[r1+4];
                al[mf][0] = cAl[r0];   al[mf][1] = cAl[r1];
                al[mf][2] = cAl[r0+4]; al[mf][3] = cAl[r1+4];
            }
#pragma unroll
            for (int nf = 0; nf < NF; nf++){
                int ib = (wc*NF*8 + nf*8 + g)*RS32 + ko + tid4;
                unsigned bh0 = cBh[ib], bh1 = cBh[ib+4];
                unsigned bl0 = cBl[ib], bl1 = cBl[ib+4];
#pragma unroll
                for (int mf = 0; mf < 4; mf++){
                    asm volatile(
                        "mma.sync.aligned.m16n8k16.row.col.f32.bf16.bf16.f32 "
                        "{%0,%1,%2,%3}, {%4,%5,%6,%7}, {%8,%9}, {%0,%1,%2,%3};"
                        : "+f"(acc[mf][nf][0]), "+f"(acc[mf][nf][1]),
                          "+f"(acc[mf][nf][2]), "+f"(acc[mf][nf][3])
                        : "r"(ah[mf][0]), "r"(ah[mf][1]), "r"(ah[mf][2]), "r"(ah[mf][3]),
                          "r"(bl0), "r"(bl1));
                    asm volatile(
                        "mma.sync.aligned.m16n8k16.row.col.f32.bf16.bf16.f32 "
                        "{%0,%1,%2,%3}, {%4,%5,%6,%7}, {%8,%9}, {%0,%1,%2,%3};"
                        : "+f"(acc[mf][nf][0]), "+f"(acc[mf][nf][1]),
                          "+f"(acc[mf][nf][2]), "+f"(acc[mf][nf][3])
                        : "r"(al[mf][0]), "r"(al[mf][1]), "r"(al[mf][2]), "r"(al[mf][3]),
                          "r"(bh0), "r"(bh1));
                    asm volatile(
                        "mma.sync.aligned.m16n8k16.row.col.f32.bf16.bf16.f32 "
                        "{%0,%1,%2,%3}, {%4,%5,%6,%7}, {%8,%9}, {%0,%1,%2,%3};"
                        : "+f"(acc[mf][nf][0]), "+f"(acc[mf][nf][1]),
                          "+f"(acc[mf][nf][2]), "+f"(acc[mf][nf][3])
                        : "r"(ah[mf][0]), "r"(ah[mf][1]), "r"(ah[mf][2]), "r"(ah[mf][3]),
                          "r"(bh0), "r"(bh1));
                }
            }
        }
        __syncthreads();
    }

    if (MODE == 2 || MODE == 3){
#pragma unroll
        for (int mf = 0; mf < 4; mf++){
            int bsg = (m0 + wr*64 + mf*16) >> 5;
#pragma unroll
            for (int nf = 0; nf < NF; nf++){
                int col = c0 + wc*NF*8 + nf*8 + tid4*2;
                float2 cv = *(const float2*)&g_cent[(size_t)bsg*COUT + col];
                acc[mf][nf][0] += cv.x; acc[mf][nf][1] += cv.y;
                acc[mf][nf][2] += cv.x; acc[mf][nf][3] += cv.y;
            }
        }
    }

    if (!MM){
#pragma unroll
        for (int mf = 0; mf < 4; mf++){
            int row0 = m0 + wr*64 + mf*16 + g;
#pragma unroll
            for (int nf = 0; nf < NF; nf++){
                int col = c0 + wc*NF*8 + nf*8 + tid4*2;
                *(float2*)&Out[(size_t)row0*COUT + col]     = make_float2(acc[mf][nf][0], acc[mf][nf][1]);
                *(float2*)&Out[(size_t)(row0+8)*COUT + col] = make_float2(acc[mf][nf][2], acc[mf][nf][3]);
            }
        }
    } else {
#pragma unroll
        for (int gi = 0; gi < 2; gi++){
#pragma unroll
            for (int nf = 0; nf < NF; nf++){
#pragma unroll
                for (int j = 0; j < 2; j++){
                    float mx = fmaxf(fmaxf(acc[2*gi][nf][j],   acc[2*gi][nf][j+2]),
                                     fmaxf(acc[2*gi+1][nf][j], acc[2*gi+1][nf][j+2]));
                    float mn = fminf(fminf(acc[2*gi][nf][j],   acc[2*gi][nf][j+2]),
                                     fminf(acc[2*gi+1][nf][j], acc[2*gi+1][nf][j+2]));
#pragma unroll
                    for (int off = 4; off <= 16; off <<= 1){
                        mx = fmaxf(mx, __shfl_xor_sync(0xffffffffu, mx, off));
                        mn = fminf(mn, __shfl_xor_sync(0xffffffffu, mn, off));
                    }
                    if (lane < 4){
                        int col = c0 + wc*NF*8 + nf*8 + tid4*2 + j;
                        int bsg = (m0 >> 5) + wr*2 + gi;
                        g_mx[(size_t)bsg*COUT + col] = mx;
                        g_mn[(size_t)bsg*COUT + col] = mn;
                    }
                }
            }
        }
    }

    if (ST){
        float cs[NF][2], cq[NF][2];
#pragma unroll
        for (int nf = 0; nf < NF; nf++){
            cs[nf][0] = cs[nf][1] = 0.f;
            cq[nf][0] = cq[nf][1] = 0.f;
        }
#pragma unroll
        for (int mf = 0; mf < 4; mf++){
#pragma unroll
            for (int nf = 0; nf < NF; nf++){
                float a0 = acc[mf][nf][0], a1 = acc[mf][nf][1];
                float a2 = acc[mf][nf][2], a3 = acc[mf][nf][3];
                cs[nf][0] += a0 + a2;         cs[nf][1] += a1 + a3;
                cq[nf][0] += a0*a0 + a2*a2;   cq[nf][1] += a1*a1 + a3*a3;
            }
        }
#pragma unroll
        for (int off = 4; off <= 16; off <<= 1){
#pragma unroll
            for (int nf = 0; nf < NF; nf++){
                cs[nf][0] += __shfl_xor_sync(0xffffffffu, cs[nf][0], off);
                cs[nf][1] += __shfl_xor_sync(0xffffffffu, cs[nf][1], off);
                cq[nf][0] += __shfl_xor_sync(0xffffffffu, cq[nf][0], off);
                cq[nf][1] += __shfl_xor_sync(0xffffffffu, cq[nf][1], off);
            }
        }
        if (lane < 4){
#pragma unroll
            for (int nf = 0; nf < NF; nf++){
                int cl = wc*NF*8 + nf*8 + tid4*2;
                atomicAdd(&shSum[cl],   cs[nf][0]);
                atomicAdd(&shSum[cl+1], cs[nf][1]);
                atomicAdd(&shSq [cl],   cq[nf][0]);
                atomicAdd(&shSq [cl+1], cq[nf][1]);
            }
        }
        __syncthreads();
        if (t < CTILE){
            atomicAdd(&g_dsum[c0+t], (double)shSum[t]);
            atomicAdd(&g_dsq [c0+t], (double)shSq [t]);
        }
    }
}

// ---------------- finalize BN+ReLU+max from per-group raw extrema ----------------
__global__ void k_bnmax1(){
    int t = blockIdx.x*blockDim.x + threadIdx.x;
    if (t >= BB*SA*128) return;
    int c = t & 127;
    float sc = g_scale[c], sf = g_shift[c];
    float a = fmaxf(fmaf(g_mx[t], sc, sf), 0.f);
    float b = fmaxf(fmaf(g_mn[t], sc, sf), 0.f);
    g_f1[t] = fmaxf(a, b);
}

__global__ void k_bnmax2(float* __restrict__ out){
    int t = blockIdx.x*blockDim.x + threadIdx.x;
    if (t >= BB*SBp*256) return;
    int c = t & 255, bs = t >> 8;
    int b = bs >> 8, s = bs & 255;
    float sc = g_scale[c], sf = g_shift[c];
    float a  = fmaxf(fmaf(g_mx[t], sc, sf), 0.f);
    float b2 = fmaxf(fmaf(g_mn[t], sc, sf), 0.f);
    out[(size_t)b*65536 + c*256 + s] = fmaxf(a, b2);
}

// ---------------- launch ----------------
extern "C" void kernel_launch(void* const* d_in, const int* in_sizes, int n_in,
                              void* d_out, int out_size){
    (void)in_sizes; (void)n_in; (void)out_size;
    const float* x    = (const float*)d_in[0];
    const float* w1   = (const float*)d_in[1];
    const float* g1   = (const float*)d_in[2];
    const float* b1   = (const float*)d_in[3];
    const float* w2   = (const float*)d_in[4];
    const float* g2   = (const float*)d_in[5];
    const float* b2   = (const float*)d_in[6];
    const float* s1w1 = (const float*)d_in[7];
    const float* s1g1 = (const float*)d_in[8];
    const float* s1b1 = (const float*)d_in[9];
    const float* s1w2 = (const float*)d_in[10];
    const float* s1g2 = (const float*)d_in[11];
    const float* s1b2 = (const float*)d_in[12];
    const float* s2w1 = (const float*)d_in[13];
    const float* s2g1 = (const float*)d_in[14];
    const float* s2b1 = (const float*)d_in[15];
    const float* s2w2 = (const float*)d_in[16];
    const float* s2g2 = (const float*)d_in[17];
    const float* s2b2 = (const float*)d_in[18];
    float* out = (float*)d_out;

    cudaFuncSetAttribute(k_mma<2,1,0,1>, cudaFuncAttributeMaxDynamicSharedMemorySize, DSMEM_B);
    cudaFuncSetAttribute(k_mma<4,2,0,1>, cudaFuncAttributeMaxDynamicSharedMemorySize, DSMEM_B);
    cudaFuncSetAttribute(k_mma<4,3,0,1>, cudaFuncAttributeMaxDynamicSharedMemorySize, DSMEM_B);
    cudaFuncSetAttribute(k_mma<4,1,1,1>, cudaFuncAttributeMaxDynamicSharedMemorySize, DSMEM_B);
    cudaFuncSetAttribute(k_mma<4,4,0,0>, cudaFuncAttributeMaxDynamicSharedMemorySize, DSMEM_B);
    cudaFuncSetAttribute(k_mma<4,5,0,0>, cudaFuncAttributeMaxDynamicSharedMemorySize, DSMEM_B);

    k_xyzT    <<<256, 256>>>(x);
    k_prepW   <<<8,  256>>>(w2,   OW2, 2048);
    k_fps     <<<32, 512>>>(0);
    k_knn     <<<dim3(32,4), 128>>>(0);
    k_prepHalf<<<16, 256>>>(s1w1, 128, O11L, O11D, 4096);
    k_prepW   <<<32, 256>>>(s1w2, O12, 8192);
    k_prepHalf<<<64, 256>>>(s2w1, 256, O21L, O21D, 16384);
    k_prepW   <<<128,256>>>(s2w2, O22, 32768);
    k_zero    <<<1,  256>>>();
    k_fps     <<<32, 512>>>(1);
    k_knn     <<<dim3(32,2), 128>>>(1);

    // ---- stem (stats fused into k_stem1) ----
    k_stem1<<<512, 256>>>(w1);
    k_stats_final<<<1,256>>>(g1, b1, 64, 65536.0);
    k_mma<2,1,0,1><<<dim3(512,1),256,DSMEM_B>>>(0, OW2, 1, 64, 64);
    k_stats_final<<<1,256>>>(g2, b2, 64, 65536.0);
    k_ew_f<<<16384,256>>>();

    // ---- SG1 ----
    k_mma<4,4,0,0><<<dim3(128,1),256,DSMEM_B>>>(0, O11D, 2, 64, 128);    // centers
    k_mma<4,2,0,1><<<dim3(4096,1),256,DSMEM_B>>>(0, O11L, 0, 64, 128);   // nbrs + cent (+stats)
    k_stats_final<<<1,256>>>(s1g1, s1b1, 128, 524288.0);
    k_mma<4,1,1,1><<<dim3(4096,1),256,DSMEM_B>>>(0, O12, 1, 128, 128);   // GEMM2 -> minmax (+stats)
    k_stats_final<<<1,256>>>(s1g2, s1b2, 128, 524288.0);
    k_bnmax1<<<8192,256>>>();

    // ---- SG2 ----
    k_mma<4,5,0,0><<<dim3(64,2),256,DSMEM_B>>>(0, O21D, 2, 128, 256);    // centers
    k_mma<4,3,0,1><<<dim3(2048,2),256,DSMEM_B>>>(0, O21L, 0, 128, 256);  // nbrs + cent (+stats)
    k_stats_final<<<1,256>>>(s2g1, s2b1, 256, 262144.0);
    k_mma<4,1,1,1><<<dim3(2048,2),256,DSMEM_B>>>(0, O22, 1, 256, 256);   // GEMM2 -> minmax (+stats)
    k_stats_final<<<1,256>>>(s2g2, s2b2, 256, 262144.0);
    k_bnmax2<<<8192,256>>>(out);
}